// round 1
// baseline (speedup 1.0000x reference)
#include <cuda_runtime.h>
#include <cuda_bf16.h>

#define N 8192
#define D 128
#define BM 128
#define BN 128
#define BK 32
#define PADM 132          // padded BM stride in smem (132*4 bytes = 33*16 -> float4 aligned)
#define INV_N2 1.4901161193847656e-08f   // 1 / 8192^2 = 2^-26, exact in fp32

// Normalized copies of x and y (allocation-free scratch: __device__ globals).
__device__ float g_xn[N * D];
__device__ float g_yn[N * D];

// ---------------------------------------------------------------------------
// Kernel A: row-normalize x -> g_xn and y -> g_yn.
// grid = 2*N blocks of D=128 threads; block b < N handles x row b, else y row b-N.
// ---------------------------------------------------------------------------
__global__ void normalize_kernel(const float* __restrict__ x,
                                 const float* __restrict__ y) {
    int b = blockIdx.x;
    const float* src;
    float* dst;
    if (b < N) { src = x + (size_t)b * D;        dst = g_xn + (size_t)b * D; }
    else       { src = y + (size_t)(b - N) * D;  dst = g_yn + (size_t)(b - N) * D; }

    float v = src[threadIdx.x];
    float ss = v * v;
    #pragma unroll
    for (int o = 16; o > 0; o >>= 1)
        ss += __shfl_xor_sync(0xffffffffu, ss, o);

    __shared__ float wsum[4];
    int wid = threadIdx.x >> 5;
    if ((threadIdx.x & 31) == 0) wsum[wid] = ss;
    __syncthreads();
    float tot = wsum[0] + wsum[1] + wsum[2] + wsum[3];

    // EPS clamp is unreachable for this data (norms ~ sqrt(128)); tiny floor for safety.
    dst[threadIdx.x] = v * rsqrtf(fmaxf(tot, 1e-24f));
}

// ---------------------------------------------------------------------------
// Kernel B: fused sim-GEMM + CosineEmbeddingLoss reduction.
// Each block computes a 128x128 tile of sim = xn @ yn^T, applies the loss map
// (diag: 1 - s, offdiag: max(s, 0)), reduces to one partial, atomicAdd into out.
// ---------------------------------------------------------------------------
__global__ void __launch_bounds__(256, 2)
gemm_loss_kernel(float* __restrict__ out) {
    __shared__ float As[BK][PADM];   // transposed: As[k][m]
    __shared__ float Bs[BK][PADM];   // transposed: Bs[k][n]
    __shared__ float red[8];

    const int bm = blockIdx.y;
    const int bn = blockIdx.x;
    const int tid = threadIdx.x;
    const int tx = tid & 15;         // 0..15 -> n direction
    const int ty = tid >> 4;         // 0..15 -> m direction

    const float* __restrict__ xbase = g_xn + (size_t)(bm * BM) * D;
    const float* __restrict__ ybase = g_yn + (size_t)(bn * BN) * D;

    // loader mapping: 256 threads, each moves 4 float4 per matrix per k-chunk
    const int lrow = tid >> 3;       // 0..31
    const int lcol = tid & 7;        // 0..7 -> which float4 within BK=32 floats

    float acc[8][8];
    #pragma unroll
    for (int i = 0; i < 8; i++)
        #pragma unroll
        for (int j = 0; j < 8; j++)
            acc[i][j] = 0.0f;

    for (int k0 = 0; k0 < D; k0 += BK) {
        #pragma unroll
        for (int rr = 0; rr < 4; rr++) {
            int m = lrow + rr * 32;
            float4 va = *(const float4*)(xbase + (size_t)m * D + k0 + lcol * 4);
            float4 vb = *(const float4*)(ybase + (size_t)m * D + k0 + lcol * 4);
            As[lcol * 4 + 0][m] = va.x;
            As[lcol * 4 + 1][m] = va.y;
            As[lcol * 4 + 2][m] = va.z;
            As[lcol * 4 + 3][m] = va.w;
            Bs[lcol * 4 + 0][m] = vb.x;
            Bs[lcol * 4 + 1][m] = vb.y;
            Bs[lcol * 4 + 2][m] = vb.z;
            Bs[lcol * 4 + 3][m] = vb.w;
        }
        __syncthreads();

        #pragma unroll
        for (int kk = 0; kk < BK; kk++) {
            float a[8], b[8];
            *(float4*)(a)     = *(const float4*)&As[kk][ty * 8];
            *(float4*)(a + 4) = *(const float4*)&As[kk][ty * 8 + 4];
            *(float4*)(b)     = *(const float4*)&Bs[kk][tx * 8];
            *(float4*)(b + 4) = *(const float4*)&Bs[kk][tx * 8 + 4];
            #pragma unroll
            for (int i = 0; i < 8; i++)
                #pragma unroll
                for (int j = 0; j < 8; j++)
                    acc[i][j] = fmaf(a[i], b[j], acc[i][j]);
        }
        __syncthreads();
    }

    // Epilogue: loss map + thread-local sum
    const int gi0 = bm * BM + ty * 8;
    const int gj0 = bn * BN + tx * 8;
    float lsum = 0.0f;
    #pragma unroll
    for (int i = 0; i < 8; i++) {
        #pragma unroll
        for (int j = 0; j < 8; j++) {
            float s = acc[i][j];
            lsum += (gi0 + i == gj0 + j) ? (1.0f - s) : fmaxf(s, 0.0f);
        }
    }

    // Block reduction
    #pragma unroll
    for (int o = 16; o > 0; o >>= 1)
        lsum += __shfl_xor_sync(0xffffffffu, lsum, o);
    int wid = tid >> 5;
    if ((tid & 31) == 0) red[wid] = lsum;
    __syncthreads();
    if (tid == 0) {
        float tot = 0.0f;
        #pragma unroll
        for (int w = 0; w < 8; w++) tot += red[w];
        atomicAdd(out, tot * INV_N2);
    }
}

// ---------------------------------------------------------------------------
extern "C" void kernel_launch(void* const* d_in, const int* in_sizes, int n_in,
                              void* d_out, int out_size) {
    const float* x = (const float*)d_in[0];
    const float* y = (const float*)d_in[1];
    float* out = (float*)d_out;

    cudaMemsetAsync(out, 0, sizeof(float));
    normalize_kernel<<<2 * N, D>>>(x, y);
    dim3 grid(N / BN, N / BM);
    gemm_loss_kernel<<<grid, 256>>>(out);
}

// round 3
// speedup vs baseline: 5.7724x; 5.7724x over previous
#include <cuda_runtime.h>
#include <cuda_bf16.h>
#include <cstdint>

#define NROWS 8192
#define DDIM  128
#define BM    128
#define BN    128
#define INV_N2 1.4901161193847656e-08f   // 2^-26

#define ROWB   272                        // padded smem row stride in bytes (17*16)
#define SMEM_A_OFF 0
#define SMEM_B_OFF (128 * ROWB)           // 34816
#define SMEM_RED_OFF (2 * 128 * ROWB)     // 69632
#define SMEM_BYTES (SMEM_RED_OFF + 64)    // 69696

// bf16 normalized copies (scratch via __device__ globals; no allocation)
__device__ __nv_bfloat16 g_xb[NROWS * DDIM];
__device__ __nv_bfloat16 g_yb[NROWS * DDIM];

__device__ __forceinline__ uint32_t smem_u32(const void* p) {
    uint32_t a;
    asm("{ .reg .u64 t; cvta.to.shared.u64 t, %1; cvt.u32.u64 %0, t; }" : "=r"(a) : "l"(p));
    return a;
}

__device__ __forceinline__ void ldmatrix_x4(uint32_t& r0, uint32_t& r1,
                                            uint32_t& r2, uint32_t& r3, uint32_t addr) {
    asm volatile("ldmatrix.sync.aligned.m8n8.x4.shared.b16 {%0,%1,%2,%3}, [%4];"
                 : "=r"(r0), "=r"(r1), "=r"(r2), "=r"(r3) : "r"(addr));
}

__device__ __forceinline__ void mma16816(float& d0, float& d1, float& d2, float& d3,
                                         uint32_t a0, uint32_t a1, uint32_t a2, uint32_t a3,
                                         uint32_t b0, uint32_t b1) {
    asm volatile("mma.sync.aligned.m16n8k16.row.col.f32.bf16.bf16.f32 "
                 "{%0,%1,%2,%3}, {%4,%5,%6,%7}, {%8,%9}, {%0,%1,%2,%3};"
                 : "+f"(d0), "+f"(d1), "+f"(d2), "+f"(d3)
                 : "r"(a0), "r"(a1), "r"(a2), "r"(a3), "r"(b0), "r"(b1));
}

// ---------------------------------------------------------------------------
// Kernel A: normalize rows in fp32, emit bf16
// ---------------------------------------------------------------------------
__global__ void normalize_kernel(const float* __restrict__ x,
                                 const float* __restrict__ y) {
    int b = blockIdx.x;
    const float* src;
    __nv_bfloat16* dst;
    if (b < NROWS) { src = x + (size_t)b * DDIM;           dst = g_xb + (size_t)b * DDIM; }
    else           { src = y + (size_t)(b - NROWS) * DDIM; dst = g_yb + (size_t)(b - NROWS) * DDIM; }

    float v = src[threadIdx.x];
    float ss = v * v;
    #pragma unroll
    for (int o = 16; o > 0; o >>= 1) ss += __shfl_xor_sync(0xffffffffu, ss, o);

    __shared__ float wsum[4];
    int wid = threadIdx.x >> 5;
    if ((threadIdx.x & 31) == 0) wsum[wid] = ss;
    __syncthreads();
    float tot = wsum[0] + wsum[1] + wsum[2] + wsum[3];
    dst[threadIdx.x] = __float2bfloat16_rn(v * rsqrtf(fmaxf(tot, 1e-24f)));
}

// ---------------------------------------------------------------------------
// Kernel B: bf16 mma.sync GEMM tile (128x128, K=128 resident) + fused loss.
// 8 warps in 2(m) x 4(n); warp tile 64x32 = 4x4 m16n8k16 fragments.
// ---------------------------------------------------------------------------
extern __shared__ char dyn_smem[];

__global__ void __launch_bounds__(256, 2)
gemm_loss_kernel(float* __restrict__ out) {
    const int tid  = threadIdx.x;
    const int warp = tid >> 5;
    const int lane = tid & 31;
    const int bm = blockIdx.y;
    const int bn = blockIdx.x;
    const int wm = warp & 1;          // 0..1 (64-row halves)
    const int wn = warp >> 1;         // 0..3 (32-col quarters)

    char* sA = dyn_smem + SMEM_A_OFF;
    char* sB = dyn_smem + SMEM_B_OFF;

    // ---- Fill SMEM tiles (padded rows, coalesced 16B loads) ----
    {
        const uint4* __restrict__ xsrc = (const uint4*)(g_xb + (size_t)(bm * BM) * DDIM);
        const uint4* __restrict__ ysrc = (const uint4*)(g_yb + (size_t)(bn * BN) * DDIM);
        #pragma unroll
        for (int it = 0; it < 8; it++) {
            int c = it * 256 + tid;        // 0..2047 16B chunks; 16 chunks per row
            int r = c >> 4;
            int v = c & 15;
            *(uint4*)(sA + r * ROWB + v * 16) = xsrc[c];
            *(uint4*)(sB + r * ROWB + v * 16) = ysrc[c];
        }
    }
    __syncthreads();

    // ---- ldmatrix address precompute ----
    const uint32_t sA32 = smem_u32(sA);
    const uint32_t sB32 = smem_u32(sB);
    const int t8 = lane & 7;
    // A x4: matrices j0..j3 = (m0-7,k0-7),(m8-15,k0-7),(m0-7,k8-15),(m8-15,k8-15)
    const uint32_t aRow = (uint32_t)(wm * 64 + t8 + ((lane >> 3) & 1) * 8);
    const uint32_t aBase = sA32 + aRow * ROWB + (uint32_t)(lane >> 4) * 16;
    // B x4: matrices = (n0-7,k0-7),(n0-7,k8-15),(n8-15,k0-7),(n8-15,k8-15)
    const uint32_t bRow = (uint32_t)(wn * 32 + ((lane >> 4) * 8) + t8);
    const uint32_t bBase = sB32 + bRow * ROWB + (uint32_t)((lane >> 3) & 1) * 16;

    float acc[4][4][4];
    #pragma unroll
    for (int i = 0; i < 4; i++)
        #pragma unroll
        for (int j = 0; j < 4; j++)
            #pragma unroll
            for (int e = 0; e < 4; e++) acc[i][j][e] = 0.0f;

    // ---- Main loop: 8 k-steps of 16 ----
    #pragma unroll
    for (int ks = 0; ks < 8; ks++) {
        uint32_t a[4][4];
        uint32_t b[2][4];
        #pragma unroll
        for (int mt = 0; mt < 4; mt++)
            ldmatrix_x4(a[mt][0], a[mt][1], a[mt][2], a[mt][3],
                        aBase + (uint32_t)(mt * 16) * ROWB + (uint32_t)ks * 32);
        #pragma unroll
        for (int bi = 0; bi < 2; bi++)
            ldmatrix_x4(b[bi][0], b[bi][1], b[bi][2], b[bi][3],
                        bBase + (uint32_t)(bi * 16) * ROWB + (uint32_t)ks * 32);

        #pragma unroll
        for (int mt = 0; mt < 4; mt++) {
            #pragma unroll
            for (int nt = 0; nt < 4; nt++) {
                const int bi = nt >> 1;
                const int po = (nt & 1) * 2;
                mma16816(acc[mt][nt][0], acc[mt][nt][1], acc[mt][nt][2], acc[mt][nt][3],
                         a[mt][0], a[mt][1], a[mt][2], a[mt][3],
                         b[bi][po], b[bi][po + 1]);
            }
        }
    }

    // ---- Fused epilogue: diag / relu + reduce ----
    // d0: (row=lane>>2, col=(lane&3)*2)  d1: col+1  d2: row+8  d3: row+8,col+1
    const int gm0 = bm * BM + wm * 64 + (lane >> 2);
    const int gn0 = bn * BN + wn * 32 + (lane & 3) * 2;
    float lsum = 0.0f;
    #pragma unroll
    for (int mt = 0; mt < 4; mt++) {
        const int gmA = gm0 + mt * 16;
        const int gmB = gmA + 8;
        #pragma unroll
        for (int nt = 0; nt < 4; nt++) {
            const int gn = gn0 + nt * 8;
            float s0 = acc[mt][nt][0], s1 = acc[mt][nt][1];
            float s2 = acc[mt][nt][2], s3 = acc[mt][nt][3];
            lsum += (gmA == gn    ) ? (1.0f - s0) : fmaxf(s0, 0.0f);
            lsum += (gmA == gn + 1) ? (1.0f - s1) : fmaxf(s1, 0.0f);
            lsum += (gmB == gn    ) ? (1.0f - s2) : fmaxf(s2, 0.0f);
            lsum += (gmB == gn + 1) ? (1.0f - s3) : fmaxf(s3, 0.0f);
        }
    }

    #pragma unroll
    for (int o = 16; o > 0; o >>= 1) lsum += __shfl_xor_sync(0xffffffffu, lsum, o);
    float* red = (float*)(dyn_smem + SMEM_RED_OFF);
    if (lane == 0) red[warp] = lsum;
    __syncthreads();
    if (tid == 0) {
        float tot = 0.0f;
        #pragma unroll
        for (int w = 0; w < 8; w++) tot += red[w];
        atomicAdd(out, tot * INV_N2);
    }
}

// ---------------------------------------------------------------------------
extern "C" void kernel_launch(void* const* d_in, const int* in_sizes, int n_in,
                              void* d_out, int out_size) {
    const float* x = (const float*)d_in[0];
    const float* y = (const float*)d_in[1];
    float* out = (float*)d_out;

    cudaFuncSetAttribute(gemm_loss_kernel,
                         cudaFuncAttributeMaxDynamicSharedMemorySize, SMEM_BYTES);

    cudaMemsetAsync(out, 0, sizeof(float));
    normalize_kernel<<<2 * NROWS, DDIM>>>(x, y);
    dim3 grid(NROWS / BN, NROWS / BM);
    gemm_loss_kernel<<<grid, 256, SMEM_BYTES>>>(out);
}